// round 14
// baseline (speedup 1.0000x reference)
#include <cuda_runtime.h>
#include <math.h>

#define Bn 8
#define Hn 192
#define Wn 192
#define NTOT (Bn*Hn*Wn)
#define NCH 6                     // 192 rows = 6 x u32 words
#define BIGD (1 << 20)

typedef unsigned long long ull;

// mask layout: [tensor][b][col][8 words] -> one column's 6 chunk words are
// contiguous, loadable as two uint4 (words 6,7 are padding, never read).
__device__ unsigned g_mask[2][Bn][Wn][8];
__device__ float    g_part[Bn*Hn];
__device__ unsigned g_count = 0;

// ---------------------------------------------------------------------------
// Kernel A: per-column fg bitmasks. Block = (tensor, b, 32-row chunk),
// blockDim (192,2): each thread builds 16 bits; halves composed via shared.
// ---------------------------------------------------------------------------
__global__ void mask_kernel(const float* __restrict__ pred,
                            const float* __restrict__ tgt) {
    const int blk = blockIdx.x;               // t*48 + b*6 + chunk
    const int t = blk / (Bn * NCH);
    const int r = blk % (Bn * NCH);
    const int b = r / NCH;
    const int chunk = r % NCH;
    const float* src = t ? tgt : pred;
    const int w = threadIdx.x;
    const int y = threadIdx.y;                // 0 = low 16 rows, 1 = high 16
    const int h0 = chunk * 32 + y * 16;

    unsigned part = 0;
    #pragma unroll
    for (int i = 0; i < 16; ++i) {
        float v = src[(b * Hn + h0 + i) * Wn + w];
        bool fg = t ? (v > 0.5f) : (v > 0.0f);   // sigmoid(v)>0.5 <=> v>0
        part |= (unsigned)fg << i;
    }

    __shared__ unsigned sm[Wn];
    if (y == 0) sm[w] = part;
    __syncthreads();
    if (y == 1) g_mask[t][b][w][chunk] = sm[w] | (part << 16);
}

// uniform-index select over 6 words (k uniform per block; out of range -> 0)
__device__ __forceinline__ unsigned sel6(unsigned w0, unsigned w1, unsigned w2,
                                         unsigned w3, unsigned w4, unsigned w5,
                                         int k) {
    return (k == 0) ? w0 : (k == 1) ? w1 : (k == 2) ? w2 :
           (k == 3) ? w3 : (k == 4) ? w4 : (k == 5) ? w5 : 0u;
}

// exact full-range fallback: nearest set bit of 192-bit mask from row h
__device__ __forceinline__ int nearest_set3(ull m0, ull m1, ull m2,
                                            int c, int bit) {
    ull a   = (c == 0) ? m0 : ((c == 1) ? m1 : m2);
    ull dn1 = (c == 0) ? m1 : ((c == 1) ? m2 : 0ULL);
    ull dn2 = (c == 0) ? m2 : 0ULL;
    ull up1 = (c == 2) ? m1 : ((c == 1) ? m0 : 0ULL);
    ull up2 = (c == 2) ? m0 : 0ULL;

    int down, up;
    ull x = a & (~0ULL << bit);
    if (x)        down = __ffsll(x) - 1 - bit;
    else if (dn1) down = 64  + __ffsll(dn1) - 1 - bit;
    else if (dn2) down = 128 + __ffsll(dn2) - 1 - bit;
    else          down = BIGD;

    x = a << (63 - bit);
    if (x)        up = __clzll(x);
    else if (up1) up = bit + 1  + __clzll(up1);
    else if (up2) up = bit + 65 + __clzll(up2);
    else          up = BIGD;

    return min(up, down);
}

// ---------------------------------------------------------------------------
// Column distance^2 to nearest OPPOSITE-class pixel, via a 32-bit window
// centered at h (one funnel shift). Exact: a hit at distance d<=15 dominates
// anything outside the window; fallback only when window is empty (rare).
// ---------------------------------------------------------------------------
__device__ __forceinline__ float col_dist_sq(
    unsigned w0, unsigned w1, unsigned w2,
    unsigned w3, unsigned w4, unsigned w5,
    int c32, int b32, int h, bool& fg_out)
{
    unsigned cw = sel6(w0, w1, w2, w3, w4, w5, c32);
    const bool fg = (cw >> b32) & 1u;
    fg_out = fg;

    unsigned nlo = sel6(w0, w1, w2, w3, w4, w5, c32 - 1);
    unsigned nhi = sel6(w0, w1, w2, w3, w4, w5, c32 + 1);
    // W covers positions h-16 .. h+15; bit 16 = h
    unsigned W = (b32 >= 16) ? __funnelshift_r(cw, nhi, b32 - 16)
                             : __funnelshift_r(nlo, cw, b32 + 16);

    unsigned sign = fg ? 0xFFFFFFFFu : 0u;
    unsigned wmask = 0xFFFFFFFFu;               // clear out-of-image positions
    if (h < 16)  wmask &= (0xFFFFFFFFu << (16 - h));
    if (h > 176) wmask &= (0xFFFFFFFFu >> (h - 176));
    unsigned Wv = (W ^ sign) & wmask;           // set bits = opposite class

    unsigned xd = Wv >> 17;                     // positions h+1 .. h+15
    unsigned xu = Wv << 16;                     // positions h-16 .. h-1
    if (xd | xu) {
        int down = xd ? __ffs((int)xd) : 99;
        int up   = xu ? (__clz((int)xu) + 1) : 99;
        int d = min(down, up);
        return (float)(d * d);
    }
    // rare: no opposite within +-15 rows -> exact full scan
    ull s64 = fg ? ~0ULL : 0ULL;
    ull m0 = ((ull)w0 | ((ull)w1 << 32)) ^ s64;
    ull m1 = ((ull)w2 | ((ull)w3 << 32)) ^ s64;
    ull m2 = ((ull)w4 | ((ull)w5 << 32)) ^ s64;
    int d = nearest_set3(m0, m1, m2, h >> 6, h & 63);
    return (d >= BIGD) ? 1.0e12f : (float)(d * d);
}

// ---------------------------------------------------------------------------
// Kernel B: EDT identity (one of fg/bg EDT is 0 per pixel) -> one column
// distance + one windowed row-DT per tensor, fused loss + reduction.
// has_fg computed via __syncthreads_or over per-column any-bits (no global
// hasany array / loads at all).
// ---------------------------------------------------------------------------
__global__ void rowpass_kernel(const float* __restrict__ pred,
                               const float* __restrict__ tgt,
                               float* __restrict__ out) {
    const int b = blockIdx.x / Hn;
    const int h = blockIdx.x % Hn;
    const int p = threadIdx.x;
    const int c32 = h >> 5, b32 = h & 31;       // uniform per block

    __shared__ float ssq[4][3 * Wn];            // [class][pad | data | pad]
    __shared__ float wsum[6];
    __shared__ int   s_last;

    // prefetch loss inputs early
    const int idx = (b * Hn + h) * Wn + p;
    const float x  = pred[idx];
    const float tv = tgt[idx];

    // pad borders (sentinel larger than any real candidate)
    #pragma unroll
    for (int k = 0; k < 4; ++k) {
        ssq[k][p]        = 1.0e12f;
        ssq[k][p + 2*Wn] = 1.0e12f;
    }

    // column masks: two uint4 per tensor
    const uint4 pa = *(const uint4*)&g_mask[0][b][p][0];
    const uint4 pc = *(const uint4*)&g_mask[0][b][p][4];
    const uint4 ta = *(const uint4*)&g_mask[1][b][p][0];
    const uint4 tc = *(const uint4*)&g_mask[1][b][p][4];

    bool fgP, fgT;
    float dsqP = col_dist_sq(pa.x, pa.y, pa.z, pa.w, pc.x, pc.y,
                             c32, b32, h, fgP);
    float dsqT = col_dist_sq(ta.x, ta.y, ta.z, ta.w, tc.x, tc.y,
                             c32, b32, h, fgT);
    const int colanyP = (pa.x | pa.y | pa.z | pa.w | pc.x | pc.y) != 0u;
    const int colanyT = (ta.x | ta.y | ta.z | ta.w | tc.x | tc.y) != 0u;

    ssq[0][Wn + p] = fgP ? dsqP : 0.0f;         // pred fg-EDT col dist^2
    ssq[1][Wn + p] = fgP ? 0.0f : dsqP;         // pred bg-EDT col dist^2
    ssq[2][Wn + p] = fgT ? dsqT : 0.0f;
    ssq[3][Wn + p] = fgT ? 0.0f : dsqT;
    // barrier doubles as ssq publish + block-wide OR for has_fg
    const int hp = __syncthreads_or(colanyP);
    const int ht = __syncthreads_or(colanyT);

    const float* aP = (fgP ? ssq[0] : ssq[1]) + Wn + p;
    const float* aT = (fgT ? ssq[2] : ssq[3]) + Wn + p;
    float bp = aP[0];
    float bt = aT[0];

    // branchless speculative window d = 1..4
    #pragma unroll
    for (int d = 1; d <= 4; ++d) {
        float dd = (float)(d * d);
        bp = fminf(bp, dd + fminf(aP[-d], aP[d]));
        bt = fminf(bt, dd + fminf(aT[-d], aT[d]));
    }
    float bmax = fmaxf(bp, bt);

    // residual (rare): exact break d^2 >= bmax
    if (bmax > 25.0f) {
        for (int d = 5; d < Wn; ++d) {
            float dd = (float)(d * d);
            if (dd >= bmax) break;
            bp = fminf(bp, dd + fminf(aP[-d], aP[d]));
            bt = fminf(bt, dd + fminf(aT[-d], aT[d]));
            bmax = fmaxf(bp, bt);
        }
    }

    // other-class D is exactly 0 -> field = sqrt(D_own)
    float pd = sqrtf(bp) * (float)hp;
    float td = sqrtf(bt) * (float)ht;

    float sg = 1.0f / (1.0f + __expf(-x));
    float e  = sg - tv;
    e = e * e;

    float num = pd * pd + td * td;
    float den = pd + td;
    den = den * den;
    float v = e * (num / den);

    // deterministic block reduction
    #pragma unroll
    for (int o = 16; o > 0; o >>= 1)
        v += __shfl_down_sync(0xffffffffu, v, o);
    if ((p & 31) == 0) wsum[p >> 5] = v;
    __syncthreads();
    if (p == 0) {
        float s = 0.0f;
        #pragma unroll
        for (int i = 0; i < 6; ++i) s += wsum[i];
        __stcg(&g_part[blockIdx.x], s);         // straight to L2
        unsigned ticket;
        asm volatile("atom.acq_rel.gpu.global.add.u32 %0, [%1], %2;"
                     : "=r"(ticket)
                     : "l"(&g_count), "r"(1u)
                     : "memory");
        s_last = (ticket == (unsigned)(gridDim.x - 1));
    }
    __syncthreads();

    // last finishing block: deterministic fixed-order fp64 final reduction.
    if (s_last) {
        __shared__ double dsm[Wn];
        double s = 0.0;
        for (int i = p; i < Bn * Hn; i += Wn)
            s += (double)__ldcg(&g_part[i]);
        dsm[p] = s;
        __syncthreads();
        #pragma unroll
        for (int o = 96; o >= 3; o >>= 1) {     // 192->96->...->3
            if (p < o) dsm[p] += dsm[p + o];
            __syncthreads();
        }
        if (p == 0) {
            double tot = dsm[0] + dsm[1] + dsm[2];
            out[0] = (float)(tot / (double)NTOT);
            g_count = 0;
        }
    }
}

extern "C" void kernel_launch(void* const* d_in, const int* in_sizes, int n_in,
                              void* d_out, int out_size) {
    const float* pred = (const float*)d_in[0];
    const float* tgt  = (const float*)d_in[1];
    float* out = (float*)d_out;
    (void)in_sizes; (void)n_in; (void)out_size;

    dim3 mb(Wn, 2);
    mask_kernel<<<2 * Bn * NCH, mb>>>(pred, tgt);
    rowpass_kernel<<<Bn * Hn, Wn>>>(pred, tgt, out);
}